// round 2
// baseline (speedup 1.0000x reference)
#include <cuda_runtime.h>
#include <cuda_bf16.h>
#include <math.h>

// Problem constants (fixed for this dataset)
#define NN 20000
#define EE 320000
#define SED 768
#define F1 512      // H*HID = 4*128
#define H1H 4
#define HID 128
#define F2 128

// ---------------- scratch (static device globals; no allocation) -------------
__device__ float g_c1[F1];
__device__ float g_h1[(size_t)NN * F1];     // layer1 transformed features
__device__ float g_out1[(size_t)NN * F1];   // layer1 output (post bias+elu)
__device__ float g_h2[(size_t)NN * F2];     // layer2 transformed features
__device__ float g_es1[NN * H1H];
__device__ float g_ed1[NN * H1H];
__device__ float g_es2[NN];
__device__ float g_ed2[NN];
__device__ int   g_deg[NN];
__device__ int   g_off[NN + 1];
__device__ int   g_cur[NN];
__device__ int   g_perm[EE];

// ---------------- helpers ---------------------------------------------------
__device__ __forceinline__ float lrelu(float v) { return v >= 0.f ? v : 0.2f * v; }

// ---------------- c1 = sent @ W1[768:, :]  (rank-1 sentence contribution) ----
__global__ void compute_c1_kernel(const float* __restrict__ sent,
                                  const float* __restrict__ W1) {
    int j = blockIdx.x * blockDim.x + threadIdx.x;
    if (j >= F1) return;
    float acc = 0.f;
    for (int k = 0; k < SED; k++)
        acc += sent[k] * W1[(size_t)(SED + k) * F1 + j];
    g_c1[j] = acc;
}

// ---------------- tiled fp32 SGEMM: C[M,N] = A[M,K] @ B[K,N] (+bias[N]) ------
#define BM 128
#define BN 128
#define BK 8
#define TM 8
#define TN 8
__global__ __launch_bounds__(256) void sgemm_kernel(
    int M, int N, int K,
    const float* __restrict__ A, const float* __restrict__ B,
    const float* __restrict__ bias, float* __restrict__ C)
{
    __shared__ __align__(16) float As[BK][BM];
    __shared__ __align__(16) float Bs[BK][BN];

    const int cCol = blockIdx.x;   // N tile
    const int cRow = blockIdx.y;   // M tile
    const int tid  = threadIdx.x;

    const int tRow = (tid / (BN / TN)) * TM;   // 0..120
    const int tCol = (tid % (BN / TN)) * TN;   // 0..120

    const int aRow = tid / (BK / 4);           // 0..127
    const int aCol = (tid % (BK / 4)) * 4;     // 0 or 4
    const int bRow = tid / (BN / 4);           // 0..7
    const int bCol = (tid % (BN / 4)) * 4;     // 0..124

    const int mBase = cRow * BM;
    const float* Ablk = A + (size_t)mBase * K;
    const float* Bblk = B + (size_t)cCol * BN;

    float acc[TM][TN];
    #pragma unroll
    for (int i = 0; i < TM; i++)
        #pragma unroll
        for (int j = 0; j < TN; j++) acc[i][j] = 0.f;

    float regA[TM], regB[TN];

    for (int k0 = 0; k0 < K; k0 += BK) {
        float4 av;
        if (mBase + aRow < M)
            av = *(const float4*)(Ablk + (size_t)aRow * K + k0 + aCol);
        else
            av = make_float4(0.f, 0.f, 0.f, 0.f);
        As[aCol + 0][aRow] = av.x;
        As[aCol + 1][aRow] = av.y;
        As[aCol + 2][aRow] = av.z;
        As[aCol + 3][aRow] = av.w;

        float4 bv = *(const float4*)(Bblk + (size_t)(k0 + bRow) * N + bCol);
        *(float4*)&Bs[bRow][bCol] = bv;

        __syncthreads();
        #pragma unroll
        for (int kk = 0; kk < BK; kk++) {
            #pragma unroll
            for (int i = 0; i < TM; i++) regA[i] = As[kk][tRow + i];
            #pragma unroll
            for (int j = 0; j < TN; j++) regB[j] = Bs[kk][tCol + j];
            #pragma unroll
            for (int i = 0; i < TM; i++)
                #pragma unroll
                for (int j = 0; j < TN; j++)
                    acc[i][j] += regA[i] * regB[j];
        }
        __syncthreads();
    }

    #pragma unroll
    for (int i = 0; i < TM; i++) {
        int r = mBase + tRow + i;
        if (r >= M) break;
        #pragma unroll
        for (int j = 0; j < TN; j += 4) {
            int c = cCol * BN + tCol + j;
            float4 v;
            v.x = acc[i][j + 0]; v.y = acc[i][j + 1];
            v.z = acc[i][j + 2]; v.w = acc[i][j + 3];
            if (bias) {
                v.x += bias[c + 0]; v.y += bias[c + 1];
                v.z += bias[c + 2]; v.w += bias[c + 3];
            }
            *(float4*)(C + (size_t)r * N + c) = v;
        }
    }
}

// ---------------- per-node attention logits, layer 1 (H=4) -------------------
__global__ void escore1_kernel(const float* __restrict__ a_src,
                               const float* __restrict__ a_dst) {
    int n = blockIdx.x;
    int lane = threadIdx.x & 31, w = threadIdx.x >> 5;   // warp = head
    const float* row = g_h1 + (size_t)n * F1 + w * HID;
    float s = 0.f, d = 0.f;
    #pragma unroll
    for (int c = lane; c < HID; c += 32) {
        float v = row[c];
        s += v * a_src[w * HID + c];
        d += v * a_dst[w * HID + c];
    }
    #pragma unroll
    for (int o = 16; o; o >>= 1) {
        s += __shfl_xor_sync(0xffffffffu, s, o);
        d += __shfl_xor_sync(0xffffffffu, d, o);
    }
    if (lane == 0) { g_es1[n * H1H + w] = s; g_ed1[n * H1H + w] = d; }
}

// ---------------- per-node attention logits, layer 2 (H=1) -------------------
__global__ void escore2_kernel(const float* __restrict__ a_src,
                               const float* __restrict__ a_dst, int N) {
    int lane = threadIdx.x & 31, w = threadIdx.x >> 5;
    int n = blockIdx.x * 4 + w;
    if (n >= N) return;
    const float* row = g_h2 + (size_t)n * F2;
    float s = 0.f, d = 0.f;
    #pragma unroll
    for (int c = lane; c < F2; c += 32) {
        float v = row[c];
        s += v * a_src[c];
        d += v * a_dst[c];
    }
    #pragma unroll
    for (int o = 16; o; o >>= 1) {
        s += __shfl_xor_sync(0xffffffffu, s, o);
        d += __shfl_xor_sync(0xffffffffu, d, o);
    }
    if (lane == 0) { g_es2[n] = s; g_ed2[n] = d; }
}

// ---------------- CSR build ---------------------------------------------------
__global__ void zero_deg_kernel(int N) {
    int i = blockIdx.x * blockDim.x + threadIdx.x;
    if (i < N) g_deg[i] = 0;
}
__global__ void hist_kernel(const int* __restrict__ dst, int E) {
    int e = blockIdx.x * blockDim.x + threadIdx.x;
    if (e < E) atomicAdd(&g_deg[dst[e]], 1);
}
__global__ void scan_kernel(int N) {   // single block, 1024 threads
    __shared__ int wsum[32];
    __shared__ int carry;
    int tid = threadIdx.x, lane = tid & 31, w = tid >> 5;
    if (tid == 0) { carry = 0; g_off[0] = 0; }
    __syncthreads();
    for (int base = 0; base < N; base += 1024) {
        int i = base + tid;
        int v = (i < N) ? g_deg[i] : 0;
        int x = v;
        #pragma unroll
        for (int o = 1; o < 32; o <<= 1) {
            int t = __shfl_up_sync(0xffffffffu, x, o);
            if (lane >= o) x += t;
        }
        if (lane == 31) wsum[w] = x;
        __syncthreads();
        if (w == 0) {
            int y = wsum[lane];
            #pragma unroll
            for (int o = 1; o < 32; o <<= 1) {
                int t = __shfl_up_sync(0xffffffffu, y, o);
                if (lane >= o) y += t;
            }
            wsum[lane] = y;
        }
        __syncthreads();
        int incl = x + (w > 0 ? wsum[w - 1] : 0) + carry;
        if (i < N) g_off[i + 1] = incl;
        __syncthreads();
        if (tid == 1023) carry = incl;
        __syncthreads();
    }
}
__global__ void copy_cursor_kernel(int N) {
    int i = blockIdx.x * blockDim.x + threadIdx.x;
    if (i < N) g_cur[i] = g_off[i];
}
__global__ void scatter_kernel(const int* __restrict__ dst, int E) {
    int e = blockIdx.x * blockDim.x + threadIdx.x;
    if (e < E) {
        int d = dst[e];
        int p = atomicAdd(&g_cur[d], 1);
        g_perm[p] = e;
    }
}

// ---------------- layer-1 softmax + aggregation + bias + ELU -----------------
__global__ __launch_bounds__(128) void agg1_kernel(
    const int* __restrict__ srcArr, const float* __restrict__ b1)
{
    int dst = blockIdx.x, tid = threadIdx.x;
    int lane = tid & 31, w = tid >> 5;
    __shared__ float m_s[4], inv_s[4], ed_s[4];
    __shared__ float w_s[256];
    __shared__ int   src_s[64];

    int beg = g_off[dst];
    int deg = g_off[dst + 1] - beg;
    if (tid < 4) ed_s[tid] = g_ed1[dst * H1H + tid];
    __syncthreads();

    // phase A: warp w owns head w -> max, sum-exp
    float edh = ed_s[w];
    float m = -1e30f;
    for (int i = lane; i < deg; i += 32) {
        int s = srcArr[g_perm[beg + i]];
        float v = lrelu(g_es1[s * H1H + w] + edh);
        m = fmaxf(m, v);
    }
    #pragma unroll
    for (int o = 16; o; o >>= 1) m = fmaxf(m, __shfl_xor_sync(0xffffffffu, m, o));
    float sum = 0.f;
    for (int i = lane; i < deg; i += 32) {
        int s = srcArr[g_perm[beg + i]];
        float v = lrelu(g_es1[s * H1H + w] + edh);
        sum += expf(v - m);
    }
    #pragma unroll
    for (int o = 16; o; o >>= 1) sum += __shfl_xor_sync(0xffffffffu, sum, o);
    if (lane == 0) { m_s[w] = m; inv_s[w] = 1.f / (sum + 1e-16f); }
    __syncthreads();

    // phase B: chunked weighted gather; thread tid owns channels tid+128*h
    float a0 = 0.f, a1 = 0.f, a2 = 0.f, a3 = 0.f;
    for (int base = 0; base < deg; base += 64) {
        int cnt = min(64, deg - base);
        if (tid < cnt) src_s[tid] = srcArr[g_perm[beg + base + tid]];
        __syncthreads();
        for (int idx = tid; idx < cnt * 4; idx += 128) {
            int eidx = idx >> 2, h = idx & 3;
            int s = src_s[eidx];
            float v = lrelu(g_es1[s * H1H + h] + ed_s[h]);
            w_s[idx] = expf(v - m_s[h]) * inv_s[h];
        }
        __syncthreads();
        for (int eidx = 0; eidx < cnt; eidx++) {
            const float* row = g_h1 + (size_t)src_s[eidx] * F1;
            float w0 = w_s[eidx * 4 + 0], w1 = w_s[eidx * 4 + 1];
            float w2 = w_s[eidx * 4 + 2], w3 = w_s[eidx * 4 + 3];
            a0 += w0 * row[tid];
            a1 += w1 * row[tid + 128];
            a2 += w2 * row[tid + 256];
            a3 += w3 * row[tid + 384];
        }
        __syncthreads();
    }

    float o0 = a0 + b1[tid];
    float o1 = a1 + b1[tid + 128];
    float o2 = a2 + b1[tid + 256];
    float o3 = a3 + b1[tid + 384];
    size_t ob = (size_t)dst * F1;
    g_out1[ob + tid]       = o0 > 0.f ? o0 : expm1f(o0);
    g_out1[ob + tid + 128] = o1 > 0.f ? o1 : expm1f(o1);
    g_out1[ob + tid + 256] = o2 > 0.f ? o2 : expm1f(o2);
    g_out1[ob + tid + 384] = o3 > 0.f ? o3 : expm1f(o3);
}

// ---------------- layer-2 softmax + aggregation + bias -----------------------
__global__ __launch_bounds__(128) void agg2_kernel(
    const int* __restrict__ srcArr, const float* __restrict__ b2,
    float* __restrict__ out)
{
    int dst = blockIdx.x, tid = threadIdx.x;
    int lane = tid & 31, w = tid >> 5;
    __shared__ float red[4];
    __shared__ float w_s[128];
    __shared__ int   src_s[128];

    int beg = g_off[dst];
    int deg = g_off[dst + 1] - beg;
    float edv = g_ed2[dst];

    float m = -1e30f;
    for (int i = tid; i < deg; i += 128) {
        int s = srcArr[g_perm[beg + i]];
        m = fmaxf(m, lrelu(g_es2[s] + edv));
    }
    #pragma unroll
    for (int o = 16; o; o >>= 1) m = fmaxf(m, __shfl_xor_sync(0xffffffffu, m, o));
    if (lane == 0) red[w] = m;
    __syncthreads();
    m = fmaxf(fmaxf(red[0], red[1]), fmaxf(red[2], red[3]));
    __syncthreads();

    float sum = 0.f;
    for (int i = tid; i < deg; i += 128) {
        int s = srcArr[g_perm[beg + i]];
        sum += expf(lrelu(g_es2[s] + edv) - m);
    }
    #pragma unroll
    for (int o = 16; o; o >>= 1) sum += __shfl_xor_sync(0xffffffffu, sum, o);
    if (lane == 0) red[w] = sum;
    __syncthreads();
    sum = red[0] + red[1] + red[2] + red[3];
    float inv = 1.f / (sum + 1e-16f);

    float acc = 0.f;
    for (int base = 0; base < deg; base += 128) {
        int cnt = min(128, deg - base);
        __syncthreads();
        if (tid < cnt) {
            int s = srcArr[g_perm[beg + base + tid]];
            src_s[tid] = s;
            w_s[tid] = expf(lrelu(g_es2[s] + edv) - m) * inv;
        }
        __syncthreads();
        for (int eidx = 0; eidx < cnt; eidx++)
            acc += w_s[eidx] * g_h2[(size_t)src_s[eidx] * F2 + tid];
    }
    out[(size_t)dst * F2 + tid] = acc + b2[tid];
}

// ---------------- launch ------------------------------------------------------
extern "C" void kernel_launch(void* const* d_in, const int* in_sizes, int n_in,
                              void* d_out, int out_size) {
    const float* x    = (const float*)d_in[0];
    const int*   ei   = (const int*)d_in[1];
    const float* sent = (const float*)d_in[2];
    const float* W1   = (const float*)d_in[3];
    const float* a1s  = (const float*)d_in[4];
    const float* a1d  = (const float*)d_in[5];
    const float* b1   = (const float*)d_in[6];
    const float* W2   = (const float*)d_in[7];
    const float* a2s  = (const float*)d_in[8];
    const float* a2d  = (const float*)d_in[9];
    const float* b2   = (const float*)d_in[10];
    float* out = (float*)d_out;

    const int N = in_sizes[0] / SED;   // 20000
    const int E = in_sizes[1] / 2;     // 320000
    const int* srcArr = ei;            // edge_index[0]
    const int* dstArr = ei + E;        // edge_index[1]

    float* p_c1; float* p_h1; float* p_out1; float* p_h2;
    cudaGetSymbolAddress((void**)&p_c1,  g_c1);
    cudaGetSymbolAddress((void**)&p_h1,  g_h1);
    cudaGetSymbolAddress((void**)&p_out1, g_out1);
    cudaGetSymbolAddress((void**)&p_h2,  g_h2);

    // 1. sentence contribution vector
    compute_c1_kernel<<<(F1 + 255) / 256, 256>>>(sent, W1);

    // 2. h1 = x @ W1[:768] + c1
    {
        dim3 grid(F1 / BN, (N + BM - 1) / BM);
        sgemm_kernel<<<grid, 256>>>(N, F1, SED, x, W1, p_c1, p_h1);
    }

    // 3. per-node logits, layer 1
    escore1_kernel<<<N, 128>>>(a1s, a1d);

    // 4. CSR by dst (counting sort)
    zero_deg_kernel<<<(N + 255) / 256, 256>>>(N);
    hist_kernel<<<(E + 255) / 256, 256>>>(dstArr, E);
    scan_kernel<<<1, 1024>>>(N);
    copy_cursor_kernel<<<(N + 255) / 256, 256>>>(N);
    scatter_kernel<<<(E + 255) / 256, 256>>>(dstArr, E);

    // 5. layer-1 attention aggregate + bias + ELU
    agg1_kernel<<<N, 128>>>(srcArr, b1);

    // 6. h2 = out1 @ W2
    {
        dim3 grid(F2 / BN, (N + BM - 1) / BM);
        sgemm_kernel<<<grid, 256>>>(N, F2, F1, p_out1, W2, nullptr, p_h2);
    }

    // 7. per-node logits, layer 2
    escore2_kernel<<<(N + 3) / 4, 128>>>(a2s, a2d, N);

    // 8. layer-2 attention aggregate + bias -> output
    agg2_kernel<<<N, 128>>>(srcArr, b2, out);
}

// round 4
// speedup vs baseline: 1.8930x; 1.8930x over previous
#include <cuda_runtime.h>
#include <cuda_bf16.h>
#include <math.h>

// Problem constants (fixed for this dataset)
#define NN 20000
#define EE 320000
#define SED 768
#define F1 512      // H*HID = 4*128
#define H1H 4
#define HID 128
#define F2 128

// ---------------- scratch (static device globals; no allocation) -------------
__device__ float g_c1[F1];
__device__ float g_h1[(size_t)NN * F1];     // layer1 transformed features
__device__ float g_out1[(size_t)NN * F1];   // layer1 output (post bias+elu)
__device__ float g_h2[(size_t)NN * F2];     // layer2 transformed features
__device__ float g_es1[NN * H1H];
__device__ float g_ed1[NN * H1H];
__device__ float g_es2[NN];
__device__ float g_ed2[NN];
__device__ int   g_deg[NN];
__device__ int   g_off[NN + 1];
__device__ int   g_cur[NN];
__device__ int   g_perm[EE];

// ---------------- helpers ---------------------------------------------------
__device__ __forceinline__ float lrelu(float v) { return v >= 0.f ? v : 0.2f * v; }

__device__ __forceinline__ unsigned f2tf32(float f) {
    unsigned u;
    asm("cvt.rna.tf32.f32 %0, %1;\n" : "=r"(u) : "f"(f));
    return u;
}

// ---------------- c1 = sent @ W1[768:, :]  (rank-1 sentence contribution) ----
__global__ void compute_c1_kernel(const float* __restrict__ sent,
                                  const float* __restrict__ W1) {
    int j = blockIdx.x * blockDim.x + threadIdx.x;
    if (j >= F1) return;
    float acc = 0.f;
    for (int k = 0; k < SED; k++)
        acc += sent[k] * W1[(size_t)(SED + k) * F1 + j];
    g_c1[j] = acc;
}

// ---------------- tf32 tensor-core GEMM: C[M,N] = A[M,K] @ B[K,N] (+bias) ----
// BM=128, BN=128, BK=16. 256 threads = 8 warps in 2(M) x 4(N); each warp 64x32.
// mma.sync.aligned.m16n8k8.row.col.f32.tf32.tf32.f32
#define GBM 128
#define GBN 128
#define GBK 16
#define SSTR 136   // smem row stride in words: bank = (8k + m) % 32, conflict-free frags

__global__ __launch_bounds__(256) void tf32_gemm_kernel(
    int M, int N, int K,
    const float* __restrict__ A, const float* __restrict__ B,
    const float* __restrict__ bias, float* __restrict__ C)
{
    __shared__ unsigned As[GBK][SSTR];
    __shared__ unsigned Bs[GBK][SSTR];

    const int tid  = threadIdx.x;
    const int lane = tid & 31;
    const int wid  = tid >> 5;

    const int mBase = blockIdx.y * GBM;
    const int nBase = blockIdx.x * GBN;

    const int wm = (wid >> 2) * 64;    // warp row offset (0 or 64)
    const int wn = (wid & 3) * 32;     // warp col offset (0..96)

    // global->smem load indices
    const int aM  = tid >> 2;          // 0..63 (row within tile; also +64)
    const int aK4 = (tid & 3) * 4;     // k start (float4)
    const int bK  = tid >> 5;          // 0..7 (also +8)
    const int bN4 = (tid & 31) * 4;    // n start (float4)

    float acc[4][4][4];
    #pragma unroll
    for (int mt = 0; mt < 4; mt++)
        #pragma unroll
        for (int nt = 0; nt < 4; nt++)
            #pragma unroll
            for (int r = 0; r < 4; r++) acc[mt][nt][r] = 0.f;

    for (int k0 = 0; k0 < K; k0 += GBK) {
        // load A tile (128 x 16), transpose into As[k][m], convert to tf32
        #pragma unroll
        for (int half = 0; half < 2; half++) {
            int m = aM + half * 64;
            float4 v;
            if (mBase + m < M)
                v = *(const float4*)(A + (size_t)(mBase + m) * K + k0 + aK4);
            else
                v = make_float4(0.f, 0.f, 0.f, 0.f);
            As[aK4 + 0][m] = f2tf32(v.x);
            As[aK4 + 1][m] = f2tf32(v.y);
            As[aK4 + 2][m] = f2tf32(v.z);
            As[aK4 + 3][m] = f2tf32(v.w);
        }
        // load B tile (16 x 128) into Bs[k][n], convert to tf32
        #pragma unroll
        for (int half = 0; half < 2; half++) {
            int k = bK + half * 8;
            float4 v = *(const float4*)(B + (size_t)(k0 + k) * N + nBase + bN4);
            Bs[k][bN4 + 0] = f2tf32(v.x);
            Bs[k][bN4 + 1] = f2tf32(v.y);
            Bs[k][bN4 + 2] = f2tf32(v.z);
            Bs[k][bN4 + 3] = f2tf32(v.w);
        }
        __syncthreads();

        #pragma unroll
        for (int kk = 0; kk < GBK; kk += 8) {
            // A fragments: 4 m-subtiles of 16 rows
            unsigned af[4][4];
            #pragma unroll
            for (int mt = 0; mt < 4; mt++) {
                int r0 = wm + mt * 16 + (lane >> 2);
                int c0 = kk + (lane & 3);
                af[mt][0] = As[c0][r0];
                af[mt][1] = As[c0][r0 + 8];
                af[mt][2] = As[c0 + 4][r0];
                af[mt][3] = As[c0 + 4][r0 + 8];
            }
            // B fragments: 4 n-subtiles of 8 cols
            unsigned bf[4][2];
            #pragma unroll
            for (int nt = 0; nt < 4; nt++) {
                int cn = wn + nt * 8 + (lane >> 2);
                int rk = kk + (lane & 3);
                bf[nt][0] = Bs[rk][cn];
                bf[nt][1] = Bs[rk + 4][cn];
            }
            #pragma unroll
            for (int mt = 0; mt < 4; mt++)
                #pragma unroll
                for (int nt = 0; nt < 4; nt++) {
                    asm volatile(
                        "mma.sync.aligned.m16n8k8.row.col.f32.tf32.tf32.f32 "
                        "{%0,%1,%2,%3}, {%4,%5,%6,%7}, {%8,%9}, {%0,%1,%2,%3};\n"
                        : "+f"(acc[mt][nt][0]), "+f"(acc[mt][nt][1]),
                          "+f"(acc[mt][nt][2]), "+f"(acc[mt][nt][3])
                        : "r"(af[mt][0]), "r"(af[mt][1]), "r"(af[mt][2]), "r"(af[mt][3]),
                          "r"(bf[nt][0]), "r"(bf[nt][1]));
                }
        }
        __syncthreads();
    }

    // epilogue: bias + store
    #pragma unroll
    for (int mt = 0; mt < 4; mt++) {
        int r0 = mBase + wm + mt * 16 + (lane >> 2);
        int r1 = r0 + 8;
        #pragma unroll
        for (int nt = 0; nt < 4; nt++) {
            int c = nBase + wn + nt * 8 + 2 * (lane & 3);
            float bx = 0.f, by = 0.f;
            if (bias) { bx = bias[c]; by = bias[c + 1]; }
            if (r0 < M) {
                float2 v = make_float2(acc[mt][nt][0] + bx, acc[mt][nt][1] + by);
                *(float2*)(C + (size_t)r0 * N + c) = v;
            }
            if (r1 < M) {
                float2 v = make_float2(acc[mt][nt][2] + bx, acc[mt][nt][3] + by);
                *(float2*)(C + (size_t)r1 * N + c) = v;
            }
        }
    }
}

// ---------------- per-node attention logits, layer 1 (H=4) -------------------
__global__ void escore1_kernel(const float* __restrict__ a_src,
                               const float* __restrict__ a_dst) {
    int n = blockIdx.x;
    int lane = threadIdx.x & 31, w = threadIdx.x >> 5;   // warp = head
    const float* row = g_h1 + (size_t)n * F1 + w * HID;
    float s = 0.f, d = 0.f;
    #pragma unroll
    for (int c = lane; c < HID; c += 32) {
        float v = row[c];
        s += v * a_src[w * HID + c];
        d += v * a_dst[w * HID + c];
    }
    #pragma unroll
    for (int o = 16; o; o >>= 1) {
        s += __shfl_xor_sync(0xffffffffu, s, o);
        d += __shfl_xor_sync(0xffffffffu, d, o);
    }
    if (lane == 0) { g_es1[n * H1H + w] = s; g_ed1[n * H1H + w] = d; }
}

// ---------------- per-node attention logits, layer 2 (H=1) -------------------
__global__ void escore2_kernel(const float* __restrict__ a_src,
                               const float* __restrict__ a_dst, int N) {
    int lane = threadIdx.x & 31, w = threadIdx.x >> 5;
    int n = blockIdx.x * 4 + w;
    if (n >= N) return;
    const float* row = g_h2 + (size_t)n * F2;
    float s = 0.f, d = 0.f;
    #pragma unroll
    for (int c = lane; c < F2; c += 32) {
        float v = row[c];
        s += v * a_src[c];
        d += v * a_dst[c];
    }
    #pragma unroll
    for (int o = 16; o; o >>= 1) {
        s += __shfl_xor_sync(0xffffffffu, s, o);
        d += __shfl_xor_sync(0xffffffffu, d, o);
    }
    if (lane == 0) { g_es2[n] = s; g_ed2[n] = d; }
}

// ---------------- CSR build ---------------------------------------------------
__global__ void zero_deg_kernel(int N) {
    int i = blockIdx.x * blockDim.x + threadIdx.x;
    if (i < N) g_deg[i] = 0;
}
__global__ void hist_kernel(const int* __restrict__ dst, int E) {
    int e = blockIdx.x * blockDim.x + threadIdx.x;
    if (e < E) atomicAdd(&g_deg[dst[e]], 1);
}
__global__ void scan_kernel(int N) {   // single block, 1024 threads
    __shared__ int wsum[32];
    __shared__ int carry;
    int tid = threadIdx.x, lane = tid & 31, w = tid >> 5;
    if (tid == 0) { carry = 0; g_off[0] = 0; }
    __syncthreads();
    for (int base = 0; base < N; base += 1024) {
        int i = base + tid;
        int v = (i < N) ? g_deg[i] : 0;
        int x = v;
        #pragma unroll
        for (int o = 1; o < 32; o <<= 1) {
            int t = __shfl_up_sync(0xffffffffu, x, o);
            if (lane >= o) x += t;
        }
        if (lane == 31) wsum[w] = x;
        __syncthreads();
        if (w == 0) {
            int y = wsum[lane];
            #pragma unroll
            for (int o = 1; o < 32; o <<= 1) {
                int t = __shfl_up_sync(0xffffffffu, y, o);
                if (lane >= o) y += t;
            }
            wsum[lane] = y;
        }
        __syncthreads();
        int incl = x + (w > 0 ? wsum[w - 1] : 0) + carry;
        if (i < N) g_off[i + 1] = incl;
        __syncthreads();
        if (tid == 1023) carry = incl;
        __syncthreads();
    }
}
__global__ void copy_cursor_kernel(int N) {
    int i = blockIdx.x * blockDim.x + threadIdx.x;
    if (i < N) g_cur[i] = g_off[i];
}
__global__ void scatter_kernel(const int* __restrict__ dst, int E) {
    int e = blockIdx.x * blockDim.x + threadIdx.x;
    if (e < E) {
        int d = dst[e];
        int p = atomicAdd(&g_cur[d], 1);
        g_perm[p] = e;
    }
}

// ---------------- layer-1 softmax + aggregation + bias + ELU -----------------
__global__ __launch_bounds__(128) void agg1_kernel(
    const int* __restrict__ srcArr, const float* __restrict__ b1)
{
    int dst = blockIdx.x, tid = threadIdx.x;
    int lane = tid & 31, w = tid >> 5;
    __shared__ float m_s[4], inv_s[4], ed_s[4];
    __shared__ float w_s[256];
    __shared__ int   src_s[64];

    int beg = g_off[dst];
    int deg = g_off[dst + 1] - beg;
    if (tid < 4) ed_s[tid] = g_ed1[dst * H1H + tid];
    __syncthreads();

    // phase A: warp w owns head w -> max, sum-exp
    float edh = ed_s[w];
    float m = -1e30f;
    for (int i = lane; i < deg; i += 32) {
        int s = srcArr[g_perm[beg + i]];
        float v = lrelu(g_es1[s * H1H + w] + edh);
        m = fmaxf(m, v);
    }
    #pragma unroll
    for (int o = 16; o; o >>= 1) m = fmaxf(m, __shfl_xor_sync(0xffffffffu, m, o));
    float sum = 0.f;
    for (int i = lane; i < deg; i += 32) {
        int s = srcArr[g_perm[beg + i]];
        float v = lrelu(g_es1[s * H1H + w] + edh);
        sum += expf(v - m);
    }
    #pragma unroll
    for (int o = 16; o; o >>= 1) sum += __shfl_xor_sync(0xffffffffu, sum, o);
    if (lane == 0) { m_s[w] = m; inv_s[w] = 1.f / (sum + 1e-16f); }
    __syncthreads();

    // phase B: chunked weighted gather; thread tid owns channels tid+128*h
    float a0 = 0.f, a1 = 0.f, a2 = 0.f, a3 = 0.f;
    for (int base = 0; base < deg; base += 64) {
        int cnt = min(64, deg - base);
        if (tid < cnt) src_s[tid] = srcArr[g_perm[beg + base + tid]];
        __syncthreads();
        for (int idx = tid; idx < cnt * 4; idx += 128) {
            int eidx = idx >> 2, h = idx & 3;
            int s = src_s[eidx];
            float v = lrelu(g_es1[s * H1H + h] + ed_s[h]);
            w_s[idx] = expf(v - m_s[h]) * inv_s[h];
        }
        __syncthreads();
        for (int eidx = 0; eidx < cnt; eidx++) {
            const float* row = g_h1 + (size_t)src_s[eidx] * F1;
            float w0 = w_s[eidx * 4 + 0], w1 = w_s[eidx * 4 + 1];
            float w2 = w_s[eidx * 4 + 2], w3 = w_s[eidx * 4 + 3];
            a0 += w0 * row[tid];
            a1 += w1 * row[tid + 128];
            a2 += w2 * row[tid + 256];
            a3 += w3 * row[tid + 384];
        }
        __syncthreads();
    }

    float o0 = a0 + b1[tid];
    float o1 = a1 + b1[tid + 128];
    float o2 = a2 + b1[tid + 256];
    float o3 = a3 + b1[tid + 384];
    size_t ob = (size_t)dst * F1;
    g_out1[ob + tid]       = o0 > 0.f ? o0 : expm1f(o0);
    g_out1[ob + tid + 128] = o1 > 0.f ? o1 : expm1f(o1);
    g_out1[ob + tid + 256] = o2 > 0.f ? o2 : expm1f(o2);
    g_out1[ob + tid + 384] = o3 > 0.f ? o3 : expm1f(o3);
}

// ---------------- layer-2 softmax + aggregation + bias -----------------------
__global__ __launch_bounds__(128) void agg2_kernel(
    const int* __restrict__ srcArr, const float* __restrict__ b2,
    float* __restrict__ out)
{
    int dst = blockIdx.x, tid = threadIdx.x;
    int lane = tid & 31, w = tid >> 5;
    __shared__ float red[4];
    __shared__ float w_s[128];
    __shared__ int   src_s[128];

    int beg = g_off[dst];
    int deg = g_off[dst + 1] - beg;
    float edv = g_ed2[dst];

    float m = -1e30f;
    for (int i = tid; i < deg; i += 128) {
        int s = srcArr[g_perm[beg + i]];
        m = fmaxf(m, lrelu(g_es2[s] + edv));
    }
    #pragma unroll
    for (int o = 16; o; o >>= 1) m = fmaxf(m, __shfl_xor_sync(0xffffffffu, m, o));
    if (lane == 0) red[w] = m;
    __syncthreads();
    m = fmaxf(fmaxf(red[0], red[1]), fmaxf(red[2], red[3]));
    __syncthreads();

    float sum = 0.f;
    for (int i = tid; i < deg; i += 128) {
        int s = srcArr[g_perm[beg + i]];
        sum += expf(lrelu(g_es2[s] + edv) - m);
    }
    #pragma unroll
    for (int o = 16; o; o >>= 1) sum += __shfl_xor_sync(0xffffffffu, sum, o);
    if (lane == 0) red[w] = sum;
    __syncthreads();
    sum = red[0] + red[1] + red[2] + red[3];
    float inv = 1.f / (sum + 1e-16f);

    float acc = 0.f;
    for (int base = 0; base < deg; base += 128) {
        int cnt = min(128, deg - base);
        __syncthreads();
        if (tid < cnt) {
            int s = srcArr[g_perm[beg + base + tid]];
            src_s[tid] = s;
            w_s[tid] = expf(lrelu(g_es2[s] + edv) - m) * inv;
        }
        __syncthreads();
        for (int eidx = 0; eidx < cnt; eidx++)
            acc += w_s[eidx] * g_h2[(size_t)src_s[eidx] * F2 + tid];
    }
    out[(size_t)dst * F2 + tid] = acc + b2[tid];
}

// ---------------- launch ------------------------------------------------------
extern "C" void kernel_launch(void* const* d_in, const int* in_sizes, int n_in,
                              void* d_out, int out_size) {
    const float* x    = (const float*)d_in[0];
    const int*   ei   = (const int*)d_in[1];
    const float* sent = (const float*)d_in[2];
    const float* W1   = (const float*)d_in[3];
    const float* a1s  = (const float*)d_in[4];
    const float* a1d  = (const float*)d_in[5];
    const float* b1   = (const float*)d_in[6];
    const float* W2   = (const float*)d_in[7];
    const float* a2s  = (const float*)d_in[8];
    const float* a2d  = (const float*)d_in[9];
    const float* b2   = (const float*)d_in[10];
    float* out = (float*)d_out;

    const int N = in_sizes[0] / SED;   // 20000
    const int E = in_sizes[1] / 2;     // 320000
    const int* srcArr = ei;            // edge_index[0]
    const int* dstArr = ei + E;        // edge_index[1]

    float* p_c1; float* p_h1; float* p_out1; float* p_h2;
    cudaGetSymbolAddress((void**)&p_c1,  g_c1);
    cudaGetSymbolAddress((void**)&p_h1,  g_h1);
    cudaGetSymbolAddress((void**)&p_out1, g_out1);
    cudaGetSymbolAddress((void**)&p_h2,  g_h2);

    // 1. sentence contribution vector (exact fp32)
    compute_c1_kernel<<<(F1 + 255) / 256, 256>>>(sent, W1);

    // 2. h1 = x @ W1[:768] + c1   (tf32 tensor cores)
    {
        dim3 grid(F1 / GBN, (N + GBM - 1) / GBM);
        tf32_gemm_kernel<<<grid, 256>>>(N, F1, SED, x, W1, p_c1, p_h1);
    }

    // 3. per-node logits, layer 1
    escore1_kernel<<<N, 128>>>(a1s, a1d);

    // 4. CSR by dst (counting sort)
    zero_deg_kernel<<<(N + 255) / 256, 256>>>(N);
    hist_kernel<<<(E + 255) / 256, 256>>>(dstArr, E);
    scan_kernel<<<1, 1024>>>(N);
    copy_cursor_kernel<<<(N + 255) / 256, 256>>>(N);
    scatter_kernel<<<(E + 255) / 256, 256>>>(dstArr, E);

    // 5. layer-1 attention aggregate + bias + ELU
    agg1_kernel<<<N, 128>>>(srcArr, b1);

    // 6. h2 = out1 @ W2   (tf32 tensor cores)
    {
        dim3 grid(F2 / GBN, (N + GBM - 1) / GBM);
        tf32_gemm_kernel<<<grid, 256>>>(N, F2, F1, p_out1, W2, nullptr, p_h2);
    }

    // 7. per-node logits, layer 2
    escore2_kernel<<<(N + 3) / 4, 128>>>(a2s, a2d, N);

    // 8. layer-2 attention aggregate + bias -> output
    agg2_kernel<<<N, 128>>>(srcArr, b2, out);
}

// round 5
// speedup vs baseline: 2.3938x; 1.2645x over previous
#include <cuda_runtime.h>
#include <cuda_bf16.h>
#include <math.h>

// Problem constants (fixed for this dataset)
#define NN 20000
#define EE 320000
#define SED 768
#define F1 512      // H*HID = 4*128
#define H1H 4
#define HID 128
#define F2 128

// ---------------- scratch (static device globals; no allocation) -------------
__device__ float g_c1[F1];
__device__ float g_h1[(size_t)NN * F1];     // layer1 transformed features
__device__ float g_out1[(size_t)NN * F1];   // layer1 output (post bias+elu)
__device__ float g_h2[(size_t)NN * F2];     // layer2 transformed features
__device__ float g_es1[NN * H1H];
__device__ float g_ed1[NN * H1H];
__device__ float g_es2[NN];
__device__ float g_ed2[NN];
__device__ int   g_deg[NN];
__device__ int   g_off[NN + 1];
__device__ int   g_cur[NN];
__device__ int   g_perm[EE];

// ---------------- helpers ---------------------------------------------------
__device__ __forceinline__ float lrelu(float v) { return v >= 0.f ? v : 0.2f * v; }

__device__ __forceinline__ unsigned f2tf32(float f) {
    unsigned u;
    asm("cvt.rna.tf32.f32 %0, %1;\n" : "=r"(u) : "f"(f));
    return u;
}

// ---------------- c1 = sent @ W1[768:, :]  (rank-1 sentence contribution) ----
__global__ void zero_c1_kernel() {
    g_c1[threadIdx.x] = 0.f;
}
// grid.x = 12 k-chunks of 64; block 512 threads (one per output column)
__global__ void c1_partial_kernel(const float* __restrict__ sent,
                                  const float* __restrict__ W1) {
    int j = threadIdx.x;
    int kBase = SED + blockIdx.x * 64;
    float acc = 0.f;
    #pragma unroll 8
    for (int k = 0; k < 64; k++)
        acc += sent[kBase - SED + blockIdx.x * 0 + blockIdx.x * 64 + k - blockIdx.x * 64] *
               0.f; // placeholder (never used; see below)
    // (rewritten cleanly below)
    acc = 0.f;
    #pragma unroll 8
    for (int k = 0; k < 64; k++) {
        int kk = blockIdx.x * 64 + k;
        acc += sent[kk] * W1[(size_t)(SED + kk) * F1 + j];
    }
    atomicAdd(&g_c1[j], acc);
}

// ---------------- tf32 tensor-core GEMM, double-buffered ---------------------
// BM=128, BN=128, BK=16. 256 threads = 8 warps in 2(M) x 4(N); each warp 64x32.
#define GBM 128
#define GBN 128
#define GBK 16
#define SSTR 136   // smem row stride in words: conflict-free fragment loads

__global__ __launch_bounds__(256) void tf32_gemm_kernel(
    int M, int N, int K,
    const float* __restrict__ A, const float* __restrict__ B,
    const float* __restrict__ bias, float* __restrict__ C)
{
    __shared__ unsigned As[2][GBK][SSTR];
    __shared__ unsigned Bs[2][GBK][SSTR];

    const int tid  = threadIdx.x;
    const int lane = tid & 31;
    const int wid  = tid >> 5;

    const int mBase = blockIdx.y * GBM;
    const int nBase = blockIdx.x * GBN;

    const int wm = (wid >> 2) * 64;    // warp row offset (0 or 64)
    const int wn = (wid & 3) * 32;     // warp col offset (0..96)

    // global->smem load indices
    const int aM  = tid >> 2;          // 0..63 (row within tile; also +64)
    const int aK4 = (tid & 3) * 4;     // k start (float4)
    const int bK  = tid >> 5;          // 0..7 (also +8)
    const int bN4 = (tid & 31) * 4;    // n start (float4)

    const bool aOk0 = (mBase + aM) < M;
    const bool aOk1 = (mBase + aM + 64) < M;

    float acc[4][4][4];
    #pragma unroll
    for (int mt = 0; mt < 4; mt++)
        #pragma unroll
        for (int nt = 0; nt < 4; nt++)
            #pragma unroll
            for (int r = 0; r < 4; r++) acc[mt][nt][r] = 0.f;

    const int NT = K / GBK;

    float4 pa[2], pb[2];
    // prologue: load tile 0
    {
        pa[0] = aOk0 ? *(const float4*)(A + (size_t)(mBase + aM) * K + aK4)
                     : make_float4(0.f, 0.f, 0.f, 0.f);
        pa[1] = aOk1 ? *(const float4*)(A + (size_t)(mBase + aM + 64) * K + aK4)
                     : make_float4(0.f, 0.f, 0.f, 0.f);
        pb[0] = *(const float4*)(B + (size_t)bK * N + nBase + bN4);
        pb[1] = *(const float4*)(B + (size_t)(bK + 8) * N + nBase + bN4);
    }
    // store tile 0 into buf 0
    {
        As[0][aK4 + 0][aM] = f2tf32(pa[0].x);
        As[0][aK4 + 1][aM] = f2tf32(pa[0].y);
        As[0][aK4 + 2][aM] = f2tf32(pa[0].z);
        As[0][aK4 + 3][aM] = f2tf32(pa[0].w);
        As[0][aK4 + 0][aM + 64] = f2tf32(pa[1].x);
        As[0][aK4 + 1][aM + 64] = f2tf32(pa[1].y);
        As[0][aK4 + 2][aM + 64] = f2tf32(pa[1].z);
        As[0][aK4 + 3][aM + 64] = f2tf32(pa[1].w);
        Bs[0][bK][bN4 + 0] = f2tf32(pb[0].x);
        Bs[0][bK][bN4 + 1] = f2tf32(pb[0].y);
        Bs[0][bK][bN4 + 2] = f2tf32(pb[0].z);
        Bs[0][bK][bN4 + 3] = f2tf32(pb[0].w);
        Bs[0][bK + 8][bN4 + 0] = f2tf32(pb[1].x);
        Bs[0][bK + 8][bN4 + 1] = f2tf32(pb[1].y);
        Bs[0][bK + 8][bN4 + 2] = f2tf32(pb[1].z);
        Bs[0][bK + 8][bN4 + 3] = f2tf32(pb[1].w);
    }
    __syncthreads();

    for (int t = 0; t < NT; t++) {
        const int cur = t & 1, nxt = cur ^ 1;
        const bool more = (t + 1) < NT;
        // prefetch tile t+1 into registers (LDG issued before compute)
        if (more) {
            int k0 = (t + 1) * GBK;
            pa[0] = aOk0 ? *(const float4*)(A + (size_t)(mBase + aM) * K + k0 + aK4)
                         : make_float4(0.f, 0.f, 0.f, 0.f);
            pa[1] = aOk1 ? *(const float4*)(A + (size_t)(mBase + aM + 64) * K + k0 + aK4)
                         : make_float4(0.f, 0.f, 0.f, 0.f);
            pb[0] = *(const float4*)(B + (size_t)(k0 + bK) * N + nBase + bN4);
            pb[1] = *(const float4*)(B + (size_t)(k0 + bK + 8) * N + nBase + bN4);
        }

        // compute on current buffer
        #pragma unroll
        for (int kk = 0; kk < GBK; kk += 8) {
            unsigned af[4][4];
            #pragma unroll
            for (int mt = 0; mt < 4; mt++) {
                int r0 = wm + mt * 16 + (lane >> 2);
                int c0 = kk + (lane & 3);
                af[mt][0] = As[cur][c0][r0];
                af[mt][1] = As[cur][c0][r0 + 8];
                af[mt][2] = As[cur][c0 + 4][r0];
                af[mt][3] = As[cur][c0 + 4][r0 + 8];
            }
            unsigned bf[4][2];
            #pragma unroll
            for (int nt = 0; nt < 4; nt++) {
                int cn = wn + nt * 8 + (lane >> 2);
                int rk = kk + (lane & 3);
                bf[nt][0] = Bs[cur][rk][cn];
                bf[nt][1] = Bs[cur][rk + 4][cn];
            }
            #pragma unroll
            for (int mt = 0; mt < 4; mt++)
                #pragma unroll
                for (int nt = 0; nt < 4; nt++) {
                    asm volatile(
                        "mma.sync.aligned.m16n8k8.row.col.f32.tf32.tf32.f32 "
                        "{%0,%1,%2,%3}, {%4,%5,%6,%7}, {%8,%9}, {%0,%1,%2,%3};\n"
                        : "+f"(acc[mt][nt][0]), "+f"(acc[mt][nt][1]),
                          "+f"(acc[mt][nt][2]), "+f"(acc[mt][nt][3])
                        : "r"(af[mt][0]), "r"(af[mt][1]), "r"(af[mt][2]), "r"(af[mt][3]),
                          "r"(bf[nt][0]), "r"(bf[nt][1]));
                }
        }

        // store prefetched tile into the other buffer
        if (more) {
            As[nxt][aK4 + 0][aM] = f2tf32(pa[0].x);
            As[nxt][aK4 + 1][aM] = f2tf32(pa[0].y);
            As[nxt][aK4 + 2][aM] = f2tf32(pa[0].z);
            As[nxt][aK4 + 3][aM] = f2tf32(pa[0].w);
            As[nxt][aK4 + 0][aM + 64] = f2tf32(pa[1].x);
            As[nxt][aK4 + 1][aM + 64] = f2tf32(pa[1].y);
            As[nxt][aK4 + 2][aM + 64] = f2tf32(pa[1].z);
            As[nxt][aK4 + 3][aM + 64] = f2tf32(pa[1].w);
            Bs[nxt][bK][bN4 + 0] = f2tf32(pb[0].x);
            Bs[nxt][bK][bN4 + 1] = f2tf32(pb[0].y);
            Bs[nxt][bK][bN4 + 2] = f2tf32(pb[0].z);
            Bs[nxt][bK][bN4 + 3] = f2tf32(pb[0].w);
            Bs[nxt][bK + 8][bN4 + 0] = f2tf32(pb[1].x);
            Bs[nxt][bK + 8][bN4 + 1] = f2tf32(pb[1].y);
            Bs[nxt][bK + 8][bN4 + 2] = f2tf32(pb[1].z);
            Bs[nxt][bK + 8][bN4 + 3] = f2tf32(pb[1].w);
        }
        __syncthreads();
    }

    // epilogue: bias + store
    #pragma unroll
    for (int mt = 0; mt < 4; mt++) {
        int r0 = mBase + wm + mt * 16 + (lane >> 2);
        int r1 = r0 + 8;
        #pragma unroll
        for (int nt = 0; nt < 4; nt++) {
            int c = nBase + wn + nt * 8 + 2 * (lane & 3);
            float bx = 0.f, by = 0.f;
            if (bias) { bx = bias[c]; by = bias[c + 1]; }
            if (r0 < M) {
                float2 v = make_float2(acc[mt][nt][0] + bx, acc[mt][nt][1] + by);
                *(float2*)(C + (size_t)r0 * N + c) = v;
            }
            if (r1 < M) {
                float2 v = make_float2(acc[mt][nt][2] + bx, acc[mt][nt][3] + by);
                *(float2*)(C + (size_t)r1 * N + c) = v;
            }
        }
    }
}

// ---------------- per-node attention logits, layer 1 (H=4) -------------------
__global__ void escore1_kernel(const float* __restrict__ a_src,
                               const float* __restrict__ a_dst) {
    int n = blockIdx.x;
    int lane = threadIdx.x & 31, w = threadIdx.x >> 5;   // warp = head
    const float* row = g_h1 + (size_t)n * F1 + w * HID;
    float s = 0.f, d = 0.f;
    #pragma unroll
    for (int c = lane; c < HID; c += 32) {
        float v = row[c];
        s += v * a_src[w * HID + c];
        d += v * a_dst[w * HID + c];
    }
    #pragma unroll
    for (int o = 16; o; o >>= 1) {
        s += __shfl_xor_sync(0xffffffffu, s, o);
        d += __shfl_xor_sync(0xffffffffu, d, o);
    }
    if (lane == 0) { g_es1[n * H1H + w] = s; g_ed1[n * H1H + w] = d; }
}

// ---------------- per-node attention logits, layer 2 (H=1) -------------------
__global__ void escore2_kernel(const float* __restrict__ a_src,
                               const float* __restrict__ a_dst, int N) {
    int lane = threadIdx.x & 31, w = threadIdx.x >> 5;
    int n = blockIdx.x * 4 + w;
    if (n >= N) return;
    const float* row = g_h2 + (size_t)n * F2;
    float s = 0.f, d = 0.f;
    #pragma unroll
    for (int c = lane; c < F2; c += 32) {
        float v = row[c];
        s += v * a_src[c];
        d += v * a_dst[c];
    }
    #pragma unroll
    for (int o = 16; o; o >>= 1) {
        s += __shfl_xor_sync(0xffffffffu, s, o);
        d += __shfl_xor_sync(0xffffffffu, d, o);
    }
    if (lane == 0) { g_es2[n] = s; g_ed2[n] = d; }
}

// ---------------- CSR build ---------------------------------------------------
__global__ void zero_deg_kernel(int N) {
    int i = blockIdx.x * blockDim.x + threadIdx.x;
    if (i < N) g_deg[i] = 0;
}
__global__ void hist_kernel(const int* __restrict__ dst, int E) {
    int e = blockIdx.x * blockDim.x + threadIdx.x;
    if (e < E) atomicAdd(&g_deg[dst[e]], 1);
}
__global__ void scan_kernel(int N) {   // single block, 1024 threads; also fills g_cur
    __shared__ int wsum[32];
    __shared__ int carry;
    int tid = threadIdx.x, lane = tid & 31, w = tid >> 5;
    if (tid == 0) { carry = 0; g_off[0] = 0; }
    __syncthreads();
    for (int base = 0; base < N; base += 1024) {
        int i = base + tid;
        int v = (i < N) ? g_deg[i] : 0;
        int x = v;
        #pragma unroll
        for (int o = 1; o < 32; o <<= 1) {
            int t = __shfl_up_sync(0xffffffffu, x, o);
            if (lane >= o) x += t;
        }
        if (lane == 31) wsum[w] = x;
        __syncthreads();
        if (w == 0) {
            int y = wsum[lane];
            #pragma unroll
            for (int o = 1; o < 32; o <<= 1) {
                int t = __shfl_up_sync(0xffffffffu, y, o);
                if (lane >= o) y += t;
            }
            wsum[lane] = y;
        }
        __syncthreads();
        int incl = x + (w > 0 ? wsum[w - 1] : 0) + carry;
        if (i < N) {
            g_off[i + 1] = incl;
            g_cur[i] = incl - v;   // exclusive prefix = cursor start
        }
        __syncthreads();
        if (tid == 1023) carry = incl;
        __syncthreads();
    }
}
__global__ void scatter_kernel(const int* __restrict__ dst, int E) {
    int e = blockIdx.x * blockDim.x + threadIdx.x;
    if (e < E) {
        int d = dst[e];
        int p = atomicAdd(&g_cur[d], 1);
        g_perm[p] = e;
    }
}

// ---------------- layer-1 softmax + aggregation + bias + ELU -----------------
__global__ __launch_bounds__(128) void agg1_kernel(
    const int* __restrict__ srcArr, const float* __restrict__ b1)
{
    int dst = blockIdx.x, tid = threadIdx.x;
    int lane = tid & 31, w = tid >> 5;
    __shared__ float m_s[4], inv_s[4], ed_s[4];
    __shared__ float w_s[256];
    __shared__ int   src_s[64];

    int beg = g_off[dst];
    int deg = g_off[dst + 1] - beg;
    if (tid < 4) ed_s[tid] = g_ed1[dst * H1H + tid];
    __syncthreads();

    // phase A: warp w owns head w -> max, sum-exp
    float edh = ed_s[w];
    float m = -1e30f;
    for (int i = lane; i < deg; i += 32) {
        int s = srcArr[g_perm[beg + i]];
        float v = lrelu(g_es1[s * H1H + w] + edh);
        m = fmaxf(m, v);
    }
    #pragma unroll
    for (int o = 16; o; o >>= 1) m = fmaxf(m, __shfl_xor_sync(0xffffffffu, m, o));
    float sum = 0.f;
    for (int i = lane; i < deg; i += 32) {
        int s = srcArr[g_perm[beg + i]];
        float v = lrelu(g_es1[s * H1H + w] + edh);
        sum += expf(v - m);
    }
    #pragma unroll
    for (int o = 16; o; o >>= 1) sum += __shfl_xor_sync(0xffffffffu, sum, o);
    if (lane == 0) { m_s[w] = m; inv_s[w] = 1.f / (sum + 1e-16f); }
    __syncthreads();

    // phase B: chunked weighted gather; thread owns 4 channels of head w
    const int c4 = lane * 4;                 // channel within head (float4)
    float4 acc = make_float4(0.f, 0.f, 0.f, 0.f);
    for (int base = 0; base < deg; base += 64) {
        int cnt = min(64, deg - base);
        if (tid < cnt) src_s[tid] = srcArr[g_perm[beg + base + tid]];
        __syncthreads();
        for (int idx = tid; idx < cnt * 4; idx += 128) {
            int eidx = idx >> 2, h = idx & 3;
            int s = src_s[eidx];
            float v = lrelu(g_es1[s * H1H + h] + ed_s[h]);
            w_s[idx] = expf(v - m_s[h]) * inv_s[h];
        }
        __syncthreads();
        #pragma unroll 4
        for (int eidx = 0; eidx < cnt; eidx++) {
            const float4 v = *(const float4*)(g_h1 + (size_t)src_s[eidx] * F1 + w * HID + c4);
            float wt = w_s[eidx * 4 + w];
            acc.x += wt * v.x; acc.y += wt * v.y;
            acc.z += wt * v.z; acc.w += wt * v.w;
        }
        __syncthreads();
    }

    int cg = w * HID + c4;
    float4 bv = *(const float4*)(b1 + cg);
    float o0 = acc.x + bv.x, o1 = acc.y + bv.y, o2 = acc.z + bv.z, o3 = acc.w + bv.w;
    float4 r;
    r.x = o0 > 0.f ? o0 : expm1f(o0);
    r.y = o1 > 0.f ? o1 : expm1f(o1);
    r.z = o2 > 0.f ? o2 : expm1f(o2);
    r.w = o3 > 0.f ? o3 : expm1f(o3);
    *(float4*)(g_out1 + (size_t)dst * F1 + cg) = r;
}

// ---------------- layer-2 softmax + aggregation + bias -----------------------
__global__ __launch_bounds__(128) void agg2_kernel(
    const int* __restrict__ srcArr, const float* __restrict__ b2,
    float* __restrict__ out)
{
    int dst = blockIdx.x, tid = threadIdx.x;
    int lane = tid & 31, w = tid >> 5;
    __shared__ float red[4];
    __shared__ float w_s[128];
    __shared__ int   src_s[128];
    __shared__ float4 red4[4][32];

    int beg = g_off[dst];
    int deg = g_off[dst + 1] - beg;
    float edv = g_ed2[dst];

    float m = -1e30f;
    for (int i = tid; i < deg; i += 128) {
        int s = srcArr[g_perm[beg + i]];
        m = fmaxf(m, lrelu(g_es2[s] + edv));
    }
    #pragma unroll
    for (int o = 16; o; o >>= 1) m = fmaxf(m, __shfl_xor_sync(0xffffffffu, m, o));
    if (lane == 0) red[w] = m;
    __syncthreads();
    m = fmaxf(fmaxf(red[0], red[1]), fmaxf(red[2], red[3]));
    __syncthreads();

    float sum = 0.f;
    for (int i = tid; i < deg; i += 128) {
        int s = srcArr[g_perm[beg + i]];
        sum += expf(lrelu(g_es2[s] + edv) - m);
    }
    #pragma unroll
    for (int o = 16; o; o >>= 1) sum += __shfl_xor_sync(0xffffffffu, sum, o);
    if (lane == 0) red[w] = sum;
    __syncthreads();
    sum = red[0] + red[1] + red[2] + red[3];
    float inv = 1.f / (sum + 1e-16f);

    // gather: warp per edge, lane owns float4 channels
    float4 acc = make_float4(0.f, 0.f, 0.f, 0.f);
    for (int base = 0; base < deg; base += 128) {
        int cnt = min(128, deg - base);
        __syncthreads();
        if (tid < cnt) {
            int s = srcArr[g_perm[beg + base + tid]];
            src_s[tid] = s;
            w_s[tid] = expf(lrelu(g_es2[s] + edv) - m) * inv;
        }
        __syncthreads();
        for (int e = w; e < cnt; e += 4) {
            int s = src_s[e];
            float wt = w_s[e];
            const float4 v = *(const float4*)(g_h2 + (size_t)s * F2 + lane * 4);
            acc.x += wt * v.x; acc.y += wt * v.y;
            acc.z += wt * v.z; acc.w += wt * v.w;
        }
    }
    red4[w][lane] = acc;
    __syncthreads();
    if (w == 0) {
        float4 a0 = red4[0][lane], a1 = red4[1][lane];
        float4 a2 = red4[2][lane], a3 = red4[3][lane];
        float4 bv = *(const float4*)(b2 + lane * 4);
        float4 r;
        r.x = a0.x + a1.x + a2.x + a3.x + bv.x;
        r.y = a0.y + a1.y + a2.y + a3.y + bv.y;
        r.z = a0.z + a1.z + a2.z + a3.z + bv.z;
        r.w = a0.w + a1.w + a2.w + a3.w + bv.w;
        *(float4*)(out + (size_t)dst * F2 + lane * 4) = r;
    }
}

// ---------------- launch ------------------------------------------------------
extern "C" void kernel_launch(void* const* d_in, const int* in_sizes, int n_in,
                              void* d_out, int out_size) {
    const float* x    = (const float*)d_in[0];
    const int*   ei   = (const int*)d_in[1];
    const float* sent = (const float*)d_in[2];
    const float* W1   = (const float*)d_in[3];
    const float* a1s  = (const float*)d_in[4];
    const float* a1d  = (const float*)d_in[5];
    const float* b1   = (const float*)d_in[6];
    const float* W2   = (const float*)d_in[7];
    const float* a2s  = (const float*)d_in[8];
    const float* a2d  = (const float*)d_in[9];
    const float* b2   = (const float*)d_in[10];
    float* out = (float*)d_out;

    const int N = in_sizes[0] / SED;   // 20000
    const int E = in_sizes[1] / 2;     // 320000
    const int* srcArr = ei;            // edge_index[0]
    const int* dstArr = ei + E;        // edge_index[1]

    float* p_c1; float* p_h1; float* p_out1; float* p_h2;
    cudaGetSymbolAddress((void**)&p_c1,  g_c1);
    cudaGetSymbolAddress((void**)&p_h1,  g_h1);
    cudaGetSymbolAddress((void**)&p_out1, g_out1);
    cudaGetSymbolAddress((void**)&p_h2,  g_h2);

    // one-time side stream + events (created on the pre-capture correctness call)
    static cudaStream_t s_side = nullptr;
    static cudaEvent_t  s_evFork = nullptr, s_evJoin = nullptr;
    static bool s_ok = false;
    if (!s_side) {
        s_ok = (cudaStreamCreateWithFlags(&s_side, cudaStreamNonBlocking) == cudaSuccess) &&
               (cudaEventCreateWithFlags(&s_evFork, cudaEventDisableTiming) == cudaSuccess) &&
               (cudaEventCreateWithFlags(&s_evJoin, cudaEventDisableTiming) == cudaSuccess);
    }

    cudaStream_t csr = s_ok ? s_side : (cudaStream_t)0;
    if (s_ok) {
        cudaEventRecord(s_evFork, 0);
        cudaStreamWaitEvent(s_side, s_evFork, 0);
    }

    // --- side chain: CSR build (depends only on edge_index) ---
    zero_deg_kernel<<<(N + 255) / 256, 256, 0, csr>>>(N);
    hist_kernel<<<(E + 255) / 256, 256, 0, csr>>>(dstArr, E);
    scan_kernel<<<1, 1024, 0, csr>>>(N);
    scatter_kernel<<<(E + 255) / 256, 256, 0, csr>>>(dstArr, E);
    if (s_ok) cudaEventRecord(s_evJoin, s_side);

    // --- main chain ---
    zero_c1_kernel<<<1, F1>>>();
    c1_partial_kernel<<<12, F1>>>(sent, W1);

    {
        dim3 grid(F1 / GBN, (N + GBM - 1) / GBM);
        tf32_gemm_kernel<<<grid, 256>>>(N, F1, SED, x, W1, p_c1, p_h1);
    }
    escore1_kernel<<<N, 128>>>(a1s, a1d);

    if (s_ok) cudaStreamWaitEvent((cudaStream_t)0, s_evJoin, 0);

    agg1_kernel<<<N, 128>>>(srcArr, b1);

    {
        dim3 grid(F2 / GBN, (N + GBM - 1) / GBM);
        tf32_gemm_kernel<<<grid, 256>>>(N, F2, F1, p_out1, W2, nullptr, p_h2);
    }
    escore2_kernel<<<(N + 3) / 4, 128>>>(a2s, a2d, N);
    agg2_kernel<<<N, 128>>>(srcArr, b2, out);
}

// round 11
// speedup vs baseline: 2.4452x; 1.0214x over previous
#include <cuda_runtime.h>
#include <cuda_bf16.h>
#include <math.h>
#include <stdint.h>

// Problem constants (fixed for this dataset)
#define NN 20000
#define EE 320000
#define SED 768
#define F1 512      // H*HID = 4*128
#define H1H 4
#define HID 128
#define F2 128

// ---------------- scratch (static device globals; no allocation) -------------
__device__ float g_c1[F1];
__device__ float g_h1[(size_t)NN * F1];
__device__ float g_out1[(size_t)NN * F1];
__device__ float g_h2[(size_t)NN * F2];
__device__ float g_es1[NN * H1H];
__device__ float g_ed1[NN * H1H];
__device__ float g_es2[NN];
__device__ float g_ed2[NN];
__device__ int   g_deg[NN];
__device__ int   g_off[NN + 1];
__device__ int   g_cur[NN];
__device__ int   g_perm[EE];

// ---------------- helpers ---------------------------------------------------
__device__ __forceinline__ float lrelu(float v) { return v >= 0.f ? v : 0.2f * v; }

__device__ __forceinline__ unsigned f2tf32(float f) {
    unsigned u;
    asm("cvt.rna.tf32.f32 %0, %1;\n" : "=r"(u) : "f"(f));
    return u;
}

// ---------------- c1 = sent @ W1[768:, :] ------------------------------------
__global__ void zero_c1_kernel() { g_c1[threadIdx.x] = 0.f; }
__global__ void c1_partial_kernel(const float* __restrict__ sent,
                                  const float* __restrict__ W1) {
    int j = threadIdx.x;
    float acc = 0.f;
    #pragma unroll 8
    for (int k = 0; k < 64; k++) {
        int kk = blockIdx.x * 64 + k;
        acc += sent[kk] * W1[(size_t)(SED + kk) * F1 + j];
    }
    atomicAdd(&g_c1[j], acc);
}

// ---------------- tf32 tensor-core GEMM, double-buffered ---------------------
// C[M,N] = A[M,K] @ B[K,N] (+bias[N]); optional fused attention logits:
// if esOut != null: esOut[row*esStride + (nBase>>7)] = sum_c v*aSrc[c]  (per block-col tile)
// BM=128, BN=128, BK=16. 256 threads = 8 warps in 2(M) x 4(N); each warp 64x32.
#define GBM 128
#define GBN 128
#define GBK 16
#define SSTR 136

__global__ __launch_bounds__(256) void tf32_gemm_kernel(
    int M, int N, int K,
    const float* __restrict__ A, const float* __restrict__ B,
    const float* __restrict__ bias, float* __restrict__ C,
    const float* __restrict__ aSrc, const float* __restrict__ aDst,
    float* __restrict__ esOut, float* __restrict__ edOut, int esStride)
{
    __shared__ unsigned As[2][GBK][SSTR];
    __shared__ unsigned Bs[2][GBK][SSTR];
    __shared__ float sEs[GBM], sEd[GBM];

    const int tid  = threadIdx.x;
    const int lane = tid & 31;
    const int wid  = tid >> 5;

    const int mBase = blockIdx.y * GBM;
    const int nBase = blockIdx.x * GBN;

    const int wm = (wid >> 2) * 64;
    const int wn = (wid & 3) * 32;

    const int aM  = tid >> 2;
    const int aK4 = (tid & 3) * 4;
    const int bK  = tid >> 5;
    const int bN4 = (tid & 31) * 4;

    const bool aOk0 = (mBase + aM) < M;
    const bool aOk1 = (mBase + aM + 64) < M;

    if (tid < GBM) { sEs[tid] = 0.f; sEd[tid] = 0.f; }

    float acc[4][4][4];
    #pragma unroll
    for (int mt = 0; mt < 4; mt++)
        #pragma unroll
        for (int nt = 0; nt < 4; nt++)
            #pragma unroll
            for (int r = 0; r < 4; r++) acc[mt][nt][r] = 0.f;

    const int NT = K / GBK;
    float4 pa[2], pb[2];
    pa[0] = aOk0 ? *(const float4*)(A + (size_t)(mBase + aM) * K + aK4)
                 : make_float4(0.f, 0.f, 0.f, 0.f);
    pa[1] = aOk1 ? *(const float4*)(A + (size_t)(mBase + aM + 64) * K + aK4)
                 : make_float4(0.f, 0.f, 0.f, 0.f);
    pb[0] = *(const float4*)(B + (size_t)bK * N + nBase + bN4);
    pb[1] = *(const float4*)(B + (size_t)(bK + 8) * N + nBase + bN4);

    As[0][aK4 + 0][aM] = f2tf32(pa[0].x);
    As[0][aK4 + 1][aM] = f2tf32(pa[0].y);
    As[0][aK4 + 2][aM] = f2tf32(pa[0].z);
    As[0][aK4 + 3][aM] = f2tf32(pa[0].w);
    As[0][aK4 + 0][aM + 64] = f2tf32(pa[1].x);
    As[0][aK4 + 1][aM + 64] = f2tf32(pa[1].y);
    As[0][aK4 + 2][aM + 64] = f2tf32(pa[1].z);
    As[0][aK4 + 3][aM + 64] = f2tf32(pa[1].w);
    Bs[0][bK][bN4 + 0] = f2tf32(pb[0].x);
    Bs[0][bK][bN4 + 1] = f2tf32(pb[0].y);
    Bs[0][bK][bN4 + 2] = f2tf32(pb[0].z);
    Bs[0][bK][bN4 + 3] = f2tf32(pb[0].w);
    Bs[0][bK + 8][bN4 + 0] = f2tf32(pb[1].x);
    Bs[0][bK + 8][bN4 + 1] = f2tf32(pb[1].y);
    Bs[0][bK + 8][bN4 + 2] = f2tf32(pb[1].z);
    Bs[0][bK + 8][bN4 + 3] = f2tf32(pb[1].w);
    __syncthreads();

    for (int t = 0; t < NT; t++) {
        const int cur = t & 1, nxt = cur ^ 1;
        const bool more = (t + 1) < NT;
        if (more) {
            int k0 = (t + 1) * GBK;
            pa[0] = aOk0 ? *(const float4*)(A + (size_t)(mBase + aM) * K + k0 + aK4)
                         : make_float4(0.f, 0.f, 0.f, 0.f);
            pa[1] = aOk1 ? *(const float4*)(A + (size_t)(mBase + aM + 64) * K + k0 + aK4)
                         : make_float4(0.f, 0.f, 0.f, 0.f);
            pb[0] = *(const float4*)(B + (size_t)(k0 + bK) * N + nBase + bN4);
            pb[1] = *(const float4*)(B + (size_t)(k0 + bK + 8) * N + nBase + bN4);
        }
        #pragma unroll
        for (int kk = 0; kk < GBK; kk += 8) {
            unsigned af[4][4];
            #pragma unroll
            for (int mt = 0; mt < 4; mt++) {
                int r0 = wm + mt * 16 + (lane >> 2);
                int c0 = kk + (lane & 3);
                af[mt][0] = As[cur][c0][r0];
                af[mt][1] = As[cur][c0][r0 + 8];
                af[mt][2] = As[cur][c0 + 4][r0];
                af[mt][3] = As[cur][c0 + 4][r0 + 8];
            }
            unsigned bf[4][2];
            #pragma unroll
            for (int nt = 0; nt < 4; nt++) {
                int cn = wn + nt * 8 + (lane >> 2);
                int rk = kk + (lane & 3);
                bf[nt][0] = Bs[cur][rk][cn];
                bf[nt][1] = Bs[cur][rk + 4][cn];
            }
            #pragma unroll
            for (int mt = 0; mt < 4; mt++)
                #pragma unroll
                for (int nt = 0; nt < 4; nt++) {
                    asm volatile(
                        "mma.sync.aligned.m16n8k8.row.col.f32.tf32.tf32.f32 "
                        "{%0,%1,%2,%3}, {%4,%5,%6,%7}, {%8,%9}, {%0,%1,%2,%3};\n"
                        : "+f"(acc[mt][nt][0]), "+f"(acc[mt][nt][1]),
                          "+f"(acc[mt][nt][2]), "+f"(acc[mt][nt][3])
                        : "r"(af[mt][0]), "r"(af[mt][1]), "r"(af[mt][2]), "r"(af[mt][3]),
                          "r"(bf[nt][0]), "r"(bf[nt][1]));
                }
        }
        if (more) {
            As[nxt][aK4 + 0][aM] = f2tf32(pa[0].x);
            As[nxt][aK4 + 1][aM] = f2tf32(pa[0].y);
            As[nxt][aK4 + 2][aM] = f2tf32(pa[0].z);
            As[nxt][aK4 + 3][aM] = f2tf32(pa[0].w);
            As[nxt][aK4 + 0][aM + 64] = f2tf32(pa[1].x);
            As[nxt][aK4 + 1][aM + 64] = f2tf32(pa[1].y);
            As[nxt][aK4 + 2][aM + 64] = f2tf32(pa[1].z);
            As[nxt][aK4 + 3][aM + 64] = f2tf32(pa[1].w);
            Bs[nxt][bK][bN4 + 0] = f2tf32(pb[0].x);
            Bs[nxt][bK][bN4 + 1] = f2tf32(pb[0].y);
            Bs[nxt][bK][bN4 + 2] = f2tf32(pb[0].z);
            Bs[nxt][bK][bN4 + 3] = f2tf32(pb[0].w);
            Bs[nxt][bK + 8][bN4 + 0] = f2tf32(pb[1].x);
            Bs[nxt][bK + 8][bN4 + 1] = f2tf32(pb[1].y);
            Bs[nxt][bK + 8][bN4 + 2] = f2tf32(pb[1].z);
            Bs[nxt][bK + 8][bN4 + 3] = f2tf32(pb[1].w);
        }
        __syncthreads();
    }

    // epilogue: bias + store + optional fused es/ed dot products
    #pragma unroll
    for (int mt = 0; mt < 4; mt++) {
        int rl0 = wm + mt * 16 + (lane >> 2);
        int rl1 = rl0 + 8;
        int r0 = mBase + rl0;
        int r1 = mBase + rl1;
        float e0 = 0.f, e1 = 0.f, d0 = 0.f, d1 = 0.f;
        #pragma unroll
        for (int nt = 0; nt < 4; nt++) {
            int c = nBase + wn + nt * 8 + 2 * (lane & 3);
            float bx = 0.f, by = 0.f;
            if (bias) { bx = bias[c]; by = bias[c + 1]; }
            float v00 = acc[mt][nt][0] + bx, v01 = acc[mt][nt][1] + by;
            float v10 = acc[mt][nt][2] + bx, v11 = acc[mt][nt][3] + by;
            if (r0 < M) *(float2*)(C + (size_t)r0 * N + c) = make_float2(v00, v01);
            if (r1 < M) *(float2*)(C + (size_t)r1 * N + c) = make_float2(v10, v11);
            if (esOut) {
                float as0 = aSrc[c], as1 = aSrc[c + 1];
                float ad0 = aDst[c], ad1 = aDst[c + 1];
                e0 += v00 * as0 + v01 * as1;
                e1 += v10 * as0 + v11 * as1;
                d0 += v00 * ad0 + v01 * ad1;
                d1 += v10 * ad0 + v11 * ad1;
            }
        }
        if (esOut) {
            e0 += __shfl_xor_sync(0xffffffffu, e0, 1);
            e0 += __shfl_xor_sync(0xffffffffu, e0, 2);
            e1 += __shfl_xor_sync(0xffffffffu, e1, 1);
            e1 += __shfl_xor_sync(0xffffffffu, e1, 2);
            d0 += __shfl_xor_sync(0xffffffffu, d0, 1);
            d0 += __shfl_xor_sync(0xffffffffu, d0, 2);
            d1 += __shfl_xor_sync(0xffffffffu, d1, 1);
            d1 += __shfl_xor_sync(0xffffffffu, d1, 2);
            if ((lane & 3) == 0) {
                atomicAdd(&sEs[rl0], e0);
                atomicAdd(&sEs[rl1], e1);
                atomicAdd(&sEd[rl0], d0);
                atomicAdd(&sEd[rl1], d1);
            }
        }
    }
    if (esOut) {
        __syncthreads();
        if (tid < GBM) {
            int gRow = mBase + tid;
            if (gRow < M) {
                int head = nBase >> 7;          // BN == head width (128)
                esOut[gRow * esStride + head] = sEs[tid];
                edOut[gRow * esStride + head] = sEd[tid];
            }
        }
    }
}

// ---------------- CSR build ---------------------------------------------------
__global__ void zero_deg_kernel(int N) {
    int i = blockIdx.x * blockDim.x + threadIdx.x;
    if (i < N) g_deg[i] = 0;
}
__global__ void hist_kernel(const int* __restrict__ dst, int E) {
    int e = blockIdx.x * blockDim.x + threadIdx.x;
    if (e < E) atomicAdd(&g_deg[dst[e]], 1);
}
__global__ void scan_kernel(int N) {
    __shared__ int wsum[32];
    __shared__ int carry;
    int tid = threadIdx.x, lane = tid & 31, w = tid >> 5;
    if (tid == 0) { carry = 0; g_off[0] = 0; }
    __syncthreads();
    for (int base = 0; base < N; base += 1024) {
        int i = base + tid;
        int v = (i < N) ? g_deg[i] : 0;
        int x = v;
        #pragma unroll
        for (int o = 1; o < 32; o <<= 1) {
            int t = __shfl_up_sync(0xffffffffu, x, o);
            if (lane >= o) x += t;
        }
        if (lane == 31) wsum[w] = x;
        __syncthreads();
        if (w == 0) {
            int y = wsum[lane];
            #pragma unroll
            for (int o = 1; o < 32; o <<= 1) {
                int t = __shfl_up_sync(0xffffffffu, y, o);
                if (lane >= o) y += t;
            }
            wsum[lane] = y;
        }
        __syncthreads();
        int incl = x + (w > 0 ? wsum[w - 1] : 0) + carry;
        if (i < N) {
            g_off[i + 1] = incl;
            g_cur[i] = incl - v;
        }
        __syncthreads();
        if (tid == 1023) carry = incl;
        __syncthreads();
    }
}
__global__ void scatter_kernel(const int* __restrict__ dst, int E) {
    int e = blockIdx.x * blockDim.x + threadIdx.x;
    if (e < E) {
        int d = dst[e];
        int p = atomicAdd(&g_cur[d], 1);
        g_perm[p] = e;
    }
}

// ---------------- layer-1 softmax + aggregation + bias + ELU -----------------
__global__ __launch_bounds__(128) void agg1_kernel(
    const int* __restrict__ srcArr, const float* __restrict__ b1)
{
    int dst = blockIdx.x, tid = threadIdx.x;
    int lane = tid & 31, w = tid >> 5;
    __shared__ float m_s[4], inv_s[4], ed_s[4];
    __shared__ float w_s[256];
    __shared__ int   src_s[64];

    int beg = g_off[dst];
    int deg = g_off[dst + 1] - beg;
    if (tid < 4) ed_s[tid] = g_ed1[dst * H1H + tid];
    __syncthreads();

    float edh = ed_s[w];
    float m = -1e30f;
    for (int i = lane; i < deg; i += 32) {
        int s = srcArr[g_perm[beg + i]];
        float v = lrelu(g_es1[s * H1H + w] + edh);
        m = fmaxf(m, v);
    }
    #pragma unroll
    for (int o = 16; o; o >>= 1) m = fmaxf(m, __shfl_xor_sync(0xffffffffu, m, o));
    float sum = 0.f;
    for (int i = lane; i < deg; i += 32) {
        int s = srcArr[g_perm[beg + i]];
        float v = lrelu(g_es1[s * H1H + w] + edh);
        sum += expf(v - m);
    }
    #pragma unroll
    for (int o = 16; o; o >>= 1) sum += __shfl_xor_sync(0xffffffffu, sum, o);
    if (lane == 0) { m_s[w] = m; inv_s[w] = 1.f / (sum + 1e-16f); }
    __syncthreads();

    const int c4 = lane * 4;
    float4 acc = make_float4(0.f, 0.f, 0.f, 0.f);
    for (int base = 0; base < deg; base += 64) {
        int cnt = min(64, deg - base);
        if (tid < cnt) src_s[tid] = srcArr[g_perm[beg + base + tid]];
        __syncthreads();
        for (int idx = tid; idx < cnt * 4; idx += 128) {
            int eidx = idx >> 2, h = idx & 3;
            int s = src_s[eidx];
            float v = lrelu(g_es1[s * H1H + h] + ed_s[h]);
            w_s[idx] = expf(v - m_s[h]) * inv_s[h];
        }
        __syncthreads();
        #pragma unroll 4
        for (int eidx = 0; eidx < cnt; eidx++) {
            const float4 v = *(const float4*)(g_h1 + (size_t)src_s[eidx] * F1 + w * HID + c4);
            float wt = w_s[eidx * 4 + w];
            acc.x += wt * v.x; acc.y += wt * v.y;
            acc.z += wt * v.z; acc.w += wt * v.w;
        }
        __syncthreads();
    }

    int cg = w * HID + c4;
    float4 bv = *(const float4*)(b1 + cg);
    float o0 = acc.x + bv.x, o1 = acc.y + bv.y, o2 = acc.z + bv.z, o3 = acc.w + bv.w;
    float4 r;
    r.x = o0 > 0.f ? o0 : expm1f(o0);
    r.y = o1 > 0.f ? o1 : expm1f(o1);
    r.z = o2 > 0.f ? o2 : expm1f(o2);
    r.w = o3 > 0.f ? o3 : expm1f(o3);
    *(float4*)(g_out1 + (size_t)dst * F1 + cg) = r;
}

// ---------------- layer-2 softmax + aggregation + bias -----------------------
__global__ __launch_bounds__(128) void agg2_kernel(
    const int* __restrict__ srcArr, const float* __restrict__ b2,
    float* __restrict__ out)
{
    int dst = blockIdx.x, tid = threadIdx.x;
    int lane = tid & 31, w = tid >> 5;
    __shared__ float red[4];
    __shared__ float w_s[128];
    __shared__ int   src_s[128];
    __shared__ float4 red4[4][32];

    int beg = g_off[dst];
    int deg = g_off[dst + 1] - beg;
    float edv = g_ed2[dst];

    float m = -1e30f;
    for (int i = tid; i < deg; i += 128) {
        int s = srcArr[g_perm[beg + i]];
        m = fmaxf(m, lrelu(g_es2[s] + edv));
    }
    #pragma unroll
    for (int o = 16; o; o >>= 1) m = fmaxf(m, __shfl_xor_sync(0xffffffffu, m, o));
    if (lane == 0) red[w] = m;
    __syncthreads();
    m = fmaxf(fmaxf(red[0], red[1]), fmaxf(red[2], red[3]));
    __syncthreads();

    float sum = 0.f;
    for (int i = tid; i < deg; i += 128) {
        int s = srcArr[g_perm[beg + i]];
        sum += expf(lrelu(g_es2[s] + edv) - m);
    }
    #pragma unroll
    for (int o = 16; o; o >>= 1) sum += __shfl_xor_sync(0xffffffffu, sum, o);
    if (lane == 0) red[w] = sum;
    __syncthreads();
    sum = red[0] + red[1] + red[2] + red[3];
    float inv = 1.f / (sum + 1e-16f);

    float4 acc = make_float4(0.f, 0.f, 0.f, 0.f);
    for (int base = 0; base < deg; base += 128) {
        int cnt = min(128, deg - base);
        __syncthreads();
        if (tid < cnt) {
            int s = srcArr[g_perm[beg + base + tid]];
            src_s[tid] = s;
            w_s[tid] = expf(lrelu(g_es2[s] + edv) - m) * inv;
        }
        __syncthreads();
        for (int e = w; e < cnt; e += 4) {
            int s = src_s[e];
            float wt = w_s[e];
            const float4 v = *(const float4*)(g_h2 + (size_t)s * F2 + lane * 4);
            acc.x += wt * v.x; acc.y += wt * v.y;
            acc.z += wt * v.z; acc.w += wt * v.w;
        }
    }
    red4[w][lane] = acc;
    __syncthreads();
    if (w == 0) {
        float4 a0 = red4[0][lane], a1 = red4[1][lane];
        float4 a2 = red4[2][lane], a3 = red4[3][lane];
        float4 bv = *(const float4*)(b2 + lane * 4);
        float4 r;
        r.x = a0.x + a1.x + a2.x + a3.x + bv.x;
        r.y = a0.y + a1.y + a2.y + a3.y + bv.y;
        r.z = a0.z + a1.z + a2.z + a3.z + bv.z;
        r.w = a0.w + a1.w + a2.w + a3.w + bv.w;
        *(float4*)(out + (size_t)dst * F2 + lane * 4) = r;
    }
}

// ---------------- launch ------------------------------------------------------
extern "C" void kernel_launch(void* const* d_in, const int* in_sizes, int n_in,
                              void* d_out, int out_size) {
    const float* x    = (const float*)d_in[0];
    const int*   ei   = (const int*)d_in[1];
    const float* sent = (const float*)d_in[2];
    const float* W1   = (const float*)d_in[3];
    const float* a1s  = (const float*)d_in[4];
    const float* a1d  = (const float*)d_in[5];
    const float* b1   = (const float*)d_in[6];
    const float* W2   = (const float*)d_in[7];
    const float* a2s  = (const float*)d_in[8];
    const float* a2d  = (const float*)d_in[9];
    const float* b2   = (const float*)d_in[10];
    float* out = (float*)d_out;

    const int N = in_sizes[0] / SED;   // 20000
    const int E = in_sizes[1] / 2;     // 320000
    const int* srcArr = ei;
    const int* dstArr = ei + E;

    float* p_c1; float* p_h1; float* p_out1; float* p_h2;
    float* p_es1; float* p_ed1; float* p_es2; float* p_ed2;
    cudaGetSymbolAddress((void**)&p_c1,   g_c1);
    cudaGetSymbolAddress((void**)&p_h1,   g_h1);
    cudaGetSymbolAddress((void**)&p_out1, g_out1);
    cudaGetSymbolAddress((void**)&p_h2,   g_h2);
    cudaGetSymbolAddress((void**)&p_es1,  g_es1);
    cudaGetSymbolAddress((void**)&p_ed1,  g_ed1);
    cudaGetSymbolAddress((void**)&p_es2,  g_es2);
    cudaGetSymbolAddress((void**)&p_ed2,  g_ed2);

    static cudaStream_t s_side = nullptr;
    static cudaEvent_t  s_evFork = nullptr, s_evJoin = nullptr;
    static bool s_ok = false;
    if (!s_side) {
        s_ok = (cudaStreamCreateWithFlags(&s_side, cudaStreamNonBlocking) == cudaSuccess) &&
               (cudaEventCreateWithFlags(&s_evFork, cudaEventDisableTiming) == cudaSuccess) &&
               (cudaEventCreateWithFlags(&s_evJoin, cudaEventDisableTiming) == cudaSuccess);
    }

    cudaStream_t csr = s_ok ? s_side : (cudaStream_t)0;
    if (s_ok) {
        cudaEventRecord(s_evFork, 0);
        cudaStreamWaitEvent(s_side, s_evFork, 0);
    }

    // launch idx 0 (side): degree zero
    zero_deg_kernel<<<(N + 255) / 256, 256, 0, csr>>>(N);

    // launch idx 1-2 (main): sentence rank-1 vector
    zero_c1_kernel<<<1, F1>>>();
    c1_partial_kernel<<<12, F1>>>(sent, W1);

    // launch idx 3 (main): GEMM1 = x @ W1[:768] + c1, fused es1/ed1
    {
        dim3 grid(F1 / GBN, (N + GBM - 1) / GBM);
        tf32_gemm_kernel<<<grid, 256>>>(N, F1, SED, x, W1, p_c1, p_h1,
                                        a1s, a1d, p_es1, p_ed1, H1H);
    }

    // remaining CSR chain on side stream (overlaps GEMM1)
    hist_kernel<<<(E + 255) / 256, 256, 0, csr>>>(dstArr, E);
    scan_kernel<<<1, 1024, 0, csr>>>(N);
    scatter_kernel<<<(E + 255) / 256, 256, 0, csr>>>(dstArr, E);
    if (s_ok) cudaEventRecord(s_evJoin, s_side);
    if (s_ok) cudaStreamWaitEvent((cudaStream_t)0, s_evJoin, 0);

    // layer-1 attention aggregate + bias + ELU
    agg1_kernel<<<N, 128>>>(srcArr, b1);

    // GEMM2 = out1 @ W2, fused es2/ed2
    {
        dim3 grid(F2 / GBN, (N + GBM - 1) / GBM);
        tf32_gemm_kernel<<<grid, 256>>>(N, F2, F1, p_out1, W2, nullptr, p_h2,
                                        a2s, a2d, p_es2, p_ed2, 1);
    }

    // layer-2 attention aggregate + bias -> output
    agg2_kernel<<<N, 128>>>(srcArr, b2, out);
}